// round 17
// baseline (speedup 1.0000x reference)
#include <cuda_runtime.h>
#include <cuda_bf16.h>
#include <cstdint>

#define THREADS 256
#define NBLOCKS 256          // 128 pb (8 patches each) x 2 o-halves

typedef unsigned long long ull;
typedef unsigned int u32;
typedef unsigned short u16;

// smem layouts (element strides, bf16):
//  xs[pi][b][K16]: b-row stride 24, pi slab stride 392  (8*392 = 3136 elems)
//  ws[pi][o][K16]: o-row stride 24, pi slab stride 784  (8*784 = 6272 elems)
#define XROW 24
#define XSLB 392
#define WROW 24
#define WSLB 784

__device__ __forceinline__ u16 bf_hi(float v, float& hf) {
    __nv_bfloat16 h = __float2bfloat16(v);
    hf = __bfloat162float(h);
    return __bfloat16_as_ushort(h);
}
__device__ __forceinline__ u16 bf_of(float v) {
    return __bfloat16_as_ushort(__float2bfloat16(v));
}
__device__ __forceinline__ ull pack4(u16 a, u16 b, u16 c, u16 d) {
    return (ull)a | ((ull)b << 16) | ((ull)c << 32) | ((ull)d << 48);
}

__global__ __launch_bounds__(THREADS, 2)
void lc1d_v14(const float* __restrict__ x,
              const float* __restrict__ w,
              float* __restrict__ out)
{
    __shared__ __align__(16) __nv_bfloat16 xs_hi[8 * XSLB];
    __shared__ __align__(16) __nv_bfloat16 xs_lo[8 * XSLB];
    __shared__ __align__(16) __nv_bfloat16 ws_hi[8 * WSLB];
    __shared__ __align__(16) __nv_bfloat16 ws_lo[8 * WSLB];

    const int tid  = threadIdx.x;
    const int pb   = blockIdx.x >> 1;       // patches 8pb .. 8pb+7
    const int oh   = blockIdx.x & 1;        // o in [32oh, 32oh+32)
    const int lane = tid & 31;
    const int wid  = tid >> 5;              // warp owns patch pi = wid
    const int g    = lane >> 2;             // groupID
    const int t    = lane & 3;              // threadID in group

    const float4* x4 = reinterpret_cast<const float4*>(x);
    const float4* w4 = reinterpret_cast<const float4*>(w);

    // D accumulators: 4 n-tiles (8 o each) x 4 f32
    float acc[4][4];
    #pragma unroll
    for (int i = 0; i < 4; ++i)
        #pragma unroll
        for (int j = 0; j < 4; ++j) acc[i][j] = 0.0f;

    // 8 K-chunks of 16 (= 4 input channels each)
    #pragma unroll 1
    for (int cc = 0; cc < 8; ++cc) {
        if (cc) __syncthreads();            // prior consume done

        // ---- stage x: 512 float4 (16b x 4cl x 8pi) ----
        #pragma unroll
        for (int it = 0; it < 2; ++it) {
            int j  = it * THREADS + tid;    // 0..511
            int pi = j & 7;
            int cl = (j >> 3) & 3;
            int b  = j >> 5;
            float4 v = x4[(size_t)(b * 32 + cc * 4 + cl) * 1024 + pb * 8 + pi];
            float hf0, hf1, hf2, hf3;
            u16 h0 = bf_hi(v.x, hf0), h1 = bf_hi(v.y, hf1);
            u16 h2 = bf_hi(v.z, hf2), h3 = bf_hi(v.w, hf3);
            ull hp = pack4(h0, h1, h2, h3);
            ull lp = pack4(bf_of(v.x - hf0), bf_of(v.y - hf1),
                           bf_of(v.z - hf2), bf_of(v.w - hf3));
            int e = pi * XSLB + b * XROW + cl * 4;   // 8B-aligned
            *reinterpret_cast<ull*>(&xs_hi[e]) = hp;
            *reinterpret_cast<ull*>(&xs_lo[e]) = lp;
        }

        // ---- stage w: 1024 float4 (32o x 4cl x 8pi) ----
        #pragma unroll
        for (int it = 0; it < 4; ++it) {
            int j  = it * THREADS + tid;    // 0..1023
            int pi = j & 7;
            int cl = (j >> 3) & 3;
            int o  = j >> 5;                // 0..31
            float4 v = w4[(size_t)((oh * 32 + o) * 32 + cc * 4 + cl) * 1024 + pb * 8 + pi];
            float hf0, hf1, hf2, hf3;
            u16 h0 = bf_hi(v.x, hf0), h1 = bf_hi(v.y, hf1);
            u16 h2 = bf_hi(v.z, hf2), h3 = bf_hi(v.w, hf3);
            ull hp = pack4(h0, h1, h2, h3);
            ull lp = pack4(bf_of(v.x - hf0), bf_of(v.y - hf1),
                           bf_of(v.z - hf2), bf_of(v.w - hf3));
            int e = pi * WSLB + o * WROW + cl * 4;
            *reinterpret_cast<ull*>(&ws_hi[e]) = hp;
            *reinterpret_cast<ull*>(&ws_lo[e]) = lp;
        }
        __syncthreads();

        // ---- consume: warp wid computes patch pi = wid ----
        {
            const int pi = wid;
            const int xb = pi * XSLB + g * XROW;
            u32 ah[4], al[4];
            ah[0] = *reinterpret_cast<const u32*>(&xs_hi[xb + 2 * t]);
            ah[1] = *reinterpret_cast<const u32*>(&xs_hi[xb + 8 * XROW + 2 * t]);
            ah[2] = *reinterpret_cast<const u32*>(&xs_hi[xb + 2 * t + 8]);
            ah[3] = *reinterpret_cast<const u32*>(&xs_hi[xb + 8 * XROW + 2 * t + 8]);
            al[0] = *reinterpret_cast<const u32*>(&xs_lo[xb + 2 * t]);
            al[1] = *reinterpret_cast<const u32*>(&xs_lo[xb + 8 * XROW + 2 * t]);
            al[2] = *reinterpret_cast<const u32*>(&xs_lo[xb + 2 * t + 8]);
            al[3] = *reinterpret_cast<const u32*>(&xs_lo[xb + 8 * XROW + 2 * t + 8]);

            #pragma unroll
            for (int tile = 0; tile < 4; ++tile) {
                const int wb = pi * WSLB + (tile * 8 + g) * WROW;
                u32 bh0 = *reinterpret_cast<const u32*>(&ws_hi[wb + 2 * t]);
                u32 bh1 = *reinterpret_cast<const u32*>(&ws_hi[wb + 2 * t + 8]);
                u32 bl0 = *reinterpret_cast<const u32*>(&ws_lo[wb + 2 * t]);
                u32 bl1 = *reinterpret_cast<const u32*>(&ws_lo[wb + 2 * t + 8]);

                float* c = acc[tile];
                asm volatile(
                    "mma.sync.aligned.m16n8k16.row.col.f32.bf16.bf16.f32 "
                    "{%0,%1,%2,%3}, {%4,%5,%6,%7}, {%8,%9}, {%0,%1,%2,%3};"
                    : "+f"(c[0]), "+f"(c[1]), "+f"(c[2]), "+f"(c[3])
                    : "r"(ah[0]), "r"(ah[1]), "r"(ah[2]), "r"(ah[3]),
                      "r"(bh0), "r"(bh1));
                asm volatile(
                    "mma.sync.aligned.m16n8k16.row.col.f32.bf16.bf16.f32 "
                    "{%0,%1,%2,%3}, {%4,%5,%6,%7}, {%8,%9}, {%0,%1,%2,%3};"
                    : "+f"(c[0]), "+f"(c[1]), "+f"(c[2]), "+f"(c[3])
                    : "r"(ah[0]), "r"(ah[1]), "r"(ah[2]), "r"(ah[3]),
                      "r"(bl0), "r"(bl1));
                asm volatile(
                    "mma.sync.aligned.m16n8k16.row.col.f32.bf16.bf16.f32 "
                    "{%0,%1,%2,%3}, {%4,%5,%6,%7}, {%8,%9}, {%0,%1,%2,%3};"
                    : "+f"(c[0]), "+f"(c[1]), "+f"(c[2]), "+f"(c[3])
                    : "r"(al[0]), "r"(al[1]), "r"(al[2]), "r"(al[3]),
                      "r"(bh0), "r"(bh1));
            }
        }
    }

    // ---- epilogue: scale and store (D mapping: c0=(g,2t) c1=(g,2t+1)
    //                c2=(g+8,2t) c3=(g+8,2t+1); n maps to o, m to b) ----
    const float sc = 0.17677669529663687f;   // 1/sqrt(32)
    const int p = pb * 8 + wid;
    #pragma unroll
    for (int tile = 0; tile < 4; ++tile) {
        const int o0 = oh * 32 + tile * 8 + 2 * t;
        const size_t r0 = (size_t)g * 65536;
        const size_t r1 = (size_t)(g + 8) * 65536;
        out[r0 + (size_t)o0 * 1024 + p]       = acc[tile][0] * sc;
        out[r0 + (size_t)(o0 + 1) * 1024 + p] = acc[tile][1] * sc;
        out[r1 + (size_t)o0 * 1024 + p]       = acc[tile][2] * sc;
        out[r1 + (size_t)(o0 + 1) * 1024 + p] = acc[tile][3] * sc;
    }
}

extern "C" void kernel_launch(void* const* d_in, const int* in_sizes, int n_in,
                              void* d_out, int out_size)
{
    const float* x = (const float*)d_in[0];   // [16, 32, 4096]
    const float* w = (const float*)d_in[1];   // [64, 32, 4096]
    float* out = (float*)d_out;               // [16, 64, 1024]
    (void)in_sizes; (void)n_in; (void)out_size;

    lc1d_v14<<<NBLOCKS, THREADS>>>(x, w, out);
}